// round 15
// baseline (speedup 1.0000x reference)
#include <cuda_runtime.h>
#include <cuda_fp16.h>
#include <math.h>

#define IN_DIM   128
#define OUT_DIM  64
#define MAX_NODES 100000
#define MAX_EDGES 1600000
#define SCAN_BLK 512

// ---- scratch (zero-initialized at load; self-resetting across calls) ----
__device__ __half g_whh[MAX_NODES * OUT_DIM];  // 12.8 MB fp16 wh
__device__ float g_srow[MAX_NODES];
__device__ float g_scol[MAX_NODES];
__device__ int   g_deg[MAX_NODES];     // reset per-node by k_reduce
__device__ int   g_start[MAX_NODES];
__device__ int   g_cursor[MAX_NODES];
__device__ int   g_total;              // chunk allocator; reset by k_reduce
__device__ int2  g_pair[MAX_EDGES];    // (col, bitcast alpha)

__device__ __forceinline__ void fma2(unsigned long long& acc,
                                     unsigned long long w,
                                     unsigned long long hh) {
    asm("fma.rn.f32x2 %0, %1, %2, %0;" : "+l"(acc) : "l"(w), "l"(hh));
}

// per-block dtype probe: warp 0 reads 32 int64 words; if edge_index is really
// int32, reinterpreted words are (lo | hi<<32) with random hi -> out of range.
__device__ __forceinline__ void probe_idx32(const void* ei, int n_nodes, int* s_flag) {
    if (threadIdx.x < 32) {
        long long v = ((const long long*)ei)[threadIdx.x];
        bool bad = (v < 0 || v >= n_nodes);
        unsigned m = __ballot_sync(0xffffffffu, bad);
        if (threadIdx.x == 0) *s_flag = (m != 0u);
    }
}

__device__ __forceinline__ long long ld_idx(const void* ei, size_t pos, int idx32) {
    if (idx32) return (long long)((const int*)ei)[pos];
    return ((const long long*)ei)[pos];
}

// ---------------------------------------------------------------------------
// GEMM: wh(fp16) = h@W + b ; s_row/s_col fused; f32x2 packed FMA.
// Tail: fused degree histogram (grid-stride) — measured-best placement.
// ---------------------------------------------------------------------------
#define HP 68
__global__ __launch_bounds__(64) void k_gemm(
    const float* __restrict__ h, const float* __restrict__ W,
    const float* __restrict__ bias, const float* __restrict__ a_w,
    const void* __restrict__ ei, int n_nodes, int n_edges)
{
    __shared__ float sH[64 * HP];        // 17408 B
    __shared__ float sW[64 * OUT_DIM];   // 16384 B
    __shared__ int s_idx32;

    const int t   = threadIdx.x;
    const int tx  = t & 7;
    const int ny  = t >> 3;
    const int node0 = blockIdx.x * 64;

    probe_idx32(ei, n_nodes, &s_idx32);  // published by the phase-loop barrier

    unsigned long long acc[4][8];
    #pragma unroll
    for (int j = 0; j < 4; j++)
        #pragma unroll
        for (int i = 0; i < 8; i++) acc[j][i] = 0ull;

    #pragma unroll
    for (int phase = 0; phase < 2; phase++) {
        for (int idx = t; idx < 64 * 16; idx += 64) {
            int row = idx >> 4, col = idx & 15;
            int node = node0 + row;
            float4 v = make_float4(0.f, 0.f, 0.f, 0.f);
            if (node < n_nodes)
                v = *(const float4*)(h + (size_t)node * IN_DIM + phase * 64 + col * 4);
            *(float4*)&sH[row * HP + col * 4] = v;
        }
        for (int idx = t; idx < 64 * 16; idx += 64)
            ((float4*)sW)[idx] = ((const float4*)W)[phase * 64 * 16 + idx];
        __syncthreads();

        #pragma unroll
        for (int k4 = 0; k4 < 16; k4++) {
            float4 hreg[8];
            #pragma unroll
            for (int i = 0; i < 8; i++)
                hreg[i] = *(const float4*)&sH[(ny + 8 * i) * HP + k4 * 4];
            #pragma unroll
            for (int kk = 0; kk < 4; kk++) {
                const float* wrow = &sW[(k4 * 4 + kk) * OUT_DIM + tx * 8];
                ulonglong2 wlo = *(const ulonglong2*)(wrow);
                ulonglong2 whi = *(const ulonglong2*)(wrow + 4);
                #pragma unroll
                for (int i = 0; i < 8; i++) {
                    float hv = (kk == 0) ? hreg[i].x : (kk == 1) ? hreg[i].y
                             : (kk == 2) ? hreg[i].z : hreg[i].w;
                    unsigned int hb = __float_as_uint(hv);
                    unsigned long long hh;
                    asm("mov.b64 %0, {%1, %1};" : "=l"(hh) : "r"(hb));
                    fma2(acc[0][i], wlo.x, hh);
                    fma2(acc[1][i], wlo.y, hh);
                    fma2(acc[2][i], whi.x, hh);
                    fma2(acc[3][i], whi.y, hh);
                }
            }
        }
        __syncthreads();
    }

    float4 b0  = *(const float4*)(bias + tx * 8);
    float4 b1  = *(const float4*)(bias + tx * 8 + 4);
    float4 a10 = *(const float4*)(a_w + tx * 8);
    float4 a11 = *(const float4*)(a_w + tx * 8 + 4);
    float4 a20 = *(const float4*)(a_w + OUT_DIM + tx * 8);
    float4 a21 = *(const float4*)(a_w + OUT_DIM + tx * 8 + 4);

    #pragma unroll
    for (int i = 0; i < 8; i++) {
        int node = node0 + ny + 8 * i;
        float o[8];
        #pragma unroll
        for (int j = 0; j < 4; j++) {
            unsigned int lo, hi;
            asm("mov.b64 {%0, %1}, %2;" : "=r"(lo), "=r"(hi) : "l"(acc[j][i]));
            o[2 * j]     = __uint_as_float(lo);
            o[2 * j + 1] = __uint_as_float(hi);
        }
        o[0] += b0.x; o[1] += b0.y; o[2] += b0.z; o[3] += b0.w;
        o[4] += b1.x; o[5] += b1.y; o[6] += b1.z; o[7] += b1.w;

        float p1 = o[0]*a10.x + o[1]*a10.y + o[2]*a10.z + o[3]*a10.w
                 + o[4]*a11.x + o[5]*a11.y + o[6]*a11.z + o[7]*a11.w;
        float p2 = o[0]*a20.x + o[1]*a20.y + o[2]*a20.z + o[3]*a20.w
                 + o[4]*a21.x + o[5]*a21.y + o[6]*a21.z + o[7]*a21.w;
        #pragma unroll
        for (int off = 4; off; off >>= 1) {
            p1 += __shfl_down_sync(0xffffffffu, p1, off, 8);
            p2 += __shfl_down_sync(0xffffffffu, p2, off, 8);
        }
        if (node < n_nodes) {
            __half2 pk[4];
            pk[0] = __floats2half2_rn(o[0], o[1]);
            pk[1] = __floats2half2_rn(o[2], o[3]);
            pk[2] = __floats2half2_rn(o[4], o[5]);
            pk[3] = __floats2half2_rn(o[6], o[7]);
            *(uint4*)(g_whh + (size_t)node * OUT_DIM + tx * 8) = *(uint4*)pk;
            if (tx == 0) { g_srow[node] = p1; g_scol[node] = p2; }
        }
    }

    // ---- fused degree histogram (grid-stride, coalesced) ----
    int idx32 = s_idx32;
    int stride = gridDim.x * 64;
    for (int e = blockIdx.x * 64 + t; e < n_edges; e += stride) {
        long long r = ld_idx(ei, e, idx32);
        if (r >= 0 && r < n_nodes) atomicAdd(&g_deg[(int)r], 1);
    }
}

// ---------------------------------------------------------------------------
// Single-kernel scan: per-block exclusive scan + atomic chunk reservation.
// Node buckets need only be disjoint contiguous ranges — placement order is
// irrelevant to the final reduction, so no ordered inter-block prefix needed.
// ---------------------------------------------------------------------------
__global__ __launch_bounds__(SCAN_BLK) void k_scan(int n) {
    __shared__ int wsum[32];
    __shared__ int s_base;
    int tid = threadIdx.x;
    int gi = blockIdx.x * SCAN_BLK + tid;
    int v = (gi < n) ? g_deg[gi] : 0;
    int lane = tid & 31, wid = tid >> 5;

    int x = v;
    #pragma unroll
    for (int o = 1; o < 32; o <<= 1) {
        int y = __shfl_up_sync(0xffffffffu, x, o);
        if (lane >= o) x += y;
    }
    if (lane == 31) wsum[wid] = x;
    __syncthreads();
    if (wid == 0) {
        int s = (lane < SCAN_BLK / 32) ? wsum[lane] : 0;
        #pragma unroll
        for (int o = 1; o < 32; o <<= 1) {
            int y = __shfl_up_sync(0xffffffffu, s, o);
            if (lane >= o) s += y;
        }
        wsum[lane] = s;
    }
    __syncthreads();
    int pre = (wid > 0) ? wsum[wid - 1] : 0;
    int incl = pre + x;

    if (tid == SCAN_BLK - 1)                      // incl == block total here
        s_base = atomicAdd(&g_total, incl);
    __syncthreads();

    if (gi < n) {
        int st = s_base + incl - v;
        g_start[gi] = st;
        g_cursor[gi] = st;
    }
}

// ---------------------------------------------------------------------------
// Fill: alpha = exp(leaky_relu(srow[r]+scol[c]+ea@a3+a_b)); bucket by row.
// ---------------------------------------------------------------------------
__global__ __launch_bounds__(256) void k_fill(
    const void* __restrict__ ei, const float* __restrict__ ea,
    const float* __restrict__ a_w, const float* __restrict__ a_b,
    int n_edges, int n_nodes)
{
    __shared__ int s_idx32;
    probe_idx32(ei, n_nodes, &s_idx32);
    __syncthreads();
    int idx32 = s_idx32;

    int e = blockIdx.x * 256 + threadIdx.x;
    if (e >= n_edges) return;
    long long r = ld_idx(ei, e, idx32);
    long long c = ld_idx(ei, (size_t)n_edges + e, idx32);
    if (r < 0 || r >= n_nodes || c < 0 || c >= n_nodes) return;

    float4 x0 = ((const float4*)ea)[e * 2];
    float4 x1 = ((const float4*)ea)[e * 2 + 1];
    float4 a30 = *(const float4*)(a_w + 2 * OUT_DIM);
    float4 a31 = *(const float4*)(a_w + 2 * OUT_DIM + 4);

    float s = g_srow[r] + g_scol[c] + a_b[0]
            + x0.x * a30.x + x0.y * a30.y + x0.z * a30.z + x0.w * a30.w
            + x1.x * a31.x + x1.y * a31.y + x1.z * a31.z + x1.w * a31.w;
    float ev = s > 0.f ? s : 0.01f * s;
    float alpha = __expf(fminf(ev, 80.f));   // overflow insurance; ratios exact

    int pos = atomicAdd(&g_cursor[(int)r], 1);
    g_pair[pos] = make_int2((int)c, __float_as_int(alpha));
}

// ---------------------------------------------------------------------------
// Reduce: 8 lanes per node (4 nodes/warp), fp16 rows gathered with 16B loads
// (measured best). Self-resets g_deg / g_total for the next call.
// ---------------------------------------------------------------------------
__global__ __launch_bounds__(256) void k_reduce(float* __restrict__ out, int n_nodes) {
    int gid = blockIdx.x * 256 + threadIdx.x;
    int node = gid >> 3;
    int lane = threadIdx.x & 7;

    if (blockIdx.x == 0 && threadIdx.x == 0) g_total = 0;   // reset allocator
    if (node >= n_nodes) return;

    int s = g_start[node];
    int d = g_deg[node];
    if (lane == 0) g_deg[node] = 0;            // reset (reads above precede in warp order)
    const uint4* wh = (const uint4*)g_whh;     // 8 uint4 per node row (128B)

    float acc[8] = {0.f, 0.f, 0.f, 0.f, 0.f, 0.f, 0.f, 0.f};
    float norm = 0.f;

#define EDGE_ACC(colv, av)                                                  \
    do {                                                                    \
        uint4 wv = wh[(unsigned)(colv) * 8u + lane];                        \
        const __half2* hp = (const __half2*)&wv;                            \
        float2 f0 = __half22float2(hp[0]);                                  \
        float2 f1 = __half22float2(hp[1]);                                  \
        float2 f2 = __half22float2(hp[2]);                                  \
        float2 f3 = __half22float2(hp[3]);                                  \
        acc[0] += (av) * f0.x; acc[1] += (av) * f0.y;                       \
        acc[2] += (av) * f1.x; acc[3] += (av) * f1.y;                       \
        acc[4] += (av) * f2.x; acc[5] += (av) * f2.y;                       \
        acc[6] += (av) * f3.x; acc[7] += (av) * f3.y;                       \
        norm += (av);                                                       \
    } while (0)

    int j = 0;
    if ((s & 1) && d > 0) {                       // peel to 16B pair alignment
        int2 p = g_pair[s];
        EDGE_ACC(p.x, __int_as_float(p.y));
        j = 1;
    }
    for (; j + 4 <= d; j += 4) {
        int4 q0 = *(const int4*)&g_pair[s + j];
        int4 q1 = *(const int4*)&g_pair[s + j + 2];
        EDGE_ACC(q0.x, __int_as_float(q0.y));
        EDGE_ACC(q0.z, __int_as_float(q0.w));
        EDGE_ACC(q1.x, __int_as_float(q1.y));
        EDGE_ACC(q1.z, __int_as_float(q1.w));
    }
    for (; j < d; j++) {
        int2 p = g_pair[s + j];
        EDGE_ACC(p.x, __int_as_float(p.y));
    }
#undef EDGE_ACC

    float inv = 1.f / (norm + 1e-8f);
    float4* dst = (float4*)(out + (size_t)node * OUT_DIM + lane * 8);
    dst[0] = make_float4(acc[0] * inv, acc[1] * inv, acc[2] * inv, acc[3] * inv);
    dst[1] = make_float4(acc[4] * inv, acc[5] * inv, acc[6] * inv, acc[7] * inv);
}

// ---------------------------------------------------------------------------
extern "C" void kernel_launch(void* const* d_in, const int* in_sizes, int n_in,
                              void* d_out, int out_size)
{
    const float* h   = (const float*)d_in[0];
    const void*  ei  = d_in[1];
    const float* ea  = (const float*)d_in[2];
    const float* w_w = (const float*)d_in[3];
    const float* w_b = (const float*)d_in[4];
    const float* a_w = (const float*)d_in[5];
    const float* a_b = (const float*)d_in[6];
    float* out = (float*)d_out;

    int n_nodes = in_sizes[0] / IN_DIM;
    int n_edges = in_sizes[2] / 8;
    int nb = (n_nodes + SCAN_BLK - 1) / SCAN_BLK;

    k_gemm  <<<(n_nodes + 63) / 64, 64>>>(h, w_w, w_b, a_w, ei, n_nodes, n_edges);
    k_scan  <<<nb, SCAN_BLK>>>(n_nodes);
    k_fill  <<<(n_edges + 255) / 256, 256>>>(ei, ea, a_w, a_b, n_edges, n_nodes);
    k_reduce<<<(n_nodes * 8 + 255) / 256, 256>>>(out, n_nodes);
}

// round 16
// speedup vs baseline: 1.0857x; 1.0857x over previous
#include <cuda_runtime.h>
#include <cuda_fp16.h>
#include <math.h>

#define IN_DIM   128
#define OUT_DIM  64
#define MAX_NODES 100000
#define MAX_EDGES 1600000
#define SCAN_BLK 512

// ---- scratch ----
__device__ __half g_whh[MAX_NODES * OUT_DIM];  // 12.8 MB fp16 wh
__device__ float g_srow[MAX_NODES];
__device__ float g_scol[MAX_NODES];
__device__ int   g_deg[MAX_NODES];
__device__ int   g_start[MAX_NODES];
__device__ int   g_cursor[MAX_NODES];
__device__ int   g_bsum[1024];
__device__ int2  g_pair[MAX_EDGES];            // (col, bitcast alpha)
__device__ int   g_idx32;                      // sticky: 1 if int32 indices

__device__ __forceinline__ long long load_idx(const void* ei, size_t pos) {
    if (g_idx32) return (long long)((const int*)ei)[pos];
    return ((const long long*)ei)[pos];
}

__device__ __forceinline__ void fma2(unsigned long long& acc,
                                     unsigned long long w,
                                     unsigned long long hh) {
    asm("fma.rn.f32x2 %0, %1, %2, %0;" : "+l"(acc) : "l"(w), "l"(hh));
}

// ---------------------------------------------------------------------------
// prep: zero degrees + parallel dtype probe (sticky flag, idempotent)
// ---------------------------------------------------------------------------
__global__ __launch_bounds__(256) void k_prep(const void* ei, int n_nodes) {
    int i = blockIdx.x * 256 + threadIdx.x;
    if (i < n_nodes) g_deg[i] = 0;
    if (blockIdx.x == 0 && threadIdx.x < 128) {
        long long v = ((const long long*)ei)[threadIdx.x];
        if (v < 0 || v >= n_nodes) g_idx32 = 1;   // never reset; data constant
    }
}

// ---------------------------------------------------------------------------
// GEMM: wh(fp16) = h@W + b ; s_row/s_col fused; f32x2 packed FMA.
// Tail: fused degree histogram (grid-stride) — measured-best placement.
// ---------------------------------------------------------------------------
#define HP 68
__global__ __launch_bounds__(64) void k_gemm(
    const float* __restrict__ h, const float* __restrict__ W,
    const float* __restrict__ bias, const float* __restrict__ a_w,
    const void* __restrict__ ei, int n_nodes, int n_edges)
{
    __shared__ float sH[64 * HP];        // 17408 B
    __shared__ float sW[64 * OUT_DIM];   // 16384 B

    const int t   = threadIdx.x;
    const int tx  = t & 7;
    const int ny  = t >> 3;
    const int node0 = blockIdx.x * 64;

    unsigned long long acc[4][8];
    #pragma unroll
    for (int j = 0; j < 4; j++)
        #pragma unroll
        for (int i = 0; i < 8; i++) acc[j][i] = 0ull;

    #pragma unroll
    for (int phase = 0; phase < 2; phase++) {
        for (int idx = t; idx < 64 * 16; idx += 64) {
            int row = idx >> 4, col = idx & 15;
            int node = node0 + row;
            float4 v = make_float4(0.f, 0.f, 0.f, 0.f);
            if (node < n_nodes)
                v = *(const float4*)(h + (size_t)node * IN_DIM + phase * 64 + col * 4);
            *(float4*)&sH[row * HP + col * 4] = v;
        }
        for (int idx = t; idx < 64 * 16; idx += 64)
            ((float4*)sW)[idx] = ((const float4*)W)[phase * 64 * 16 + idx];
        __syncthreads();

        #pragma unroll
        for (int k4 = 0; k4 < 16; k4++) {
            float4 hreg[8];
            #pragma unroll
            for (int i = 0; i < 8; i++)
                hreg[i] = *(const float4*)&sH[(ny + 8 * i) * HP + k4 * 4];
            #pragma unroll
            for (int kk = 0; kk < 4; kk++) {
                const float* wrow = &sW[(k4 * 4 + kk) * OUT_DIM + tx * 8];
                ulonglong2 wlo = *(const ulonglong2*)(wrow);
                ulonglong2 whi = *(const ulonglong2*)(wrow + 4);
                #pragma unroll
                for (int i = 0; i < 8; i++) {
                    float hv = (kk == 0) ? hreg[i].x : (kk == 1) ? hreg[i].y
                             : (kk == 2) ? hreg[i].z : hreg[i].w;
                    unsigned int hb = __float_as_uint(hv);
                    unsigned long long hh;
                    asm("mov.b64 %0, {%1, %1};" : "=l"(hh) : "r"(hb));
                    fma2(acc[0][i], wlo.x, hh);
                    fma2(acc[1][i], wlo.y, hh);
                    fma2(acc[2][i], whi.x, hh);
                    fma2(acc[3][i], whi.y, hh);
                }
            }
        }
        __syncthreads();
    }

    float4 b0  = *(const float4*)(bias + tx * 8);
    float4 b1  = *(const float4*)(bias + tx * 8 + 4);
    float4 a10 = *(const float4*)(a_w + tx * 8);
    float4 a11 = *(const float4*)(a_w + tx * 8 + 4);
    float4 a20 = *(const float4*)(a_w + OUT_DIM + tx * 8);
    float4 a21 = *(const float4*)(a_w + OUT_DIM + tx * 8 + 4);

    #pragma unroll
    for (int i = 0; i < 8; i++) {
        int node = node0 + ny + 8 * i;
        float o[8];
        #pragma unroll
        for (int j = 0; j < 4; j++) {
            unsigned int lo, hi;
            asm("mov.b64 {%0, %1}, %2;" : "=r"(lo), "=r"(hi) : "l"(acc[j][i]));
            o[2 * j]     = __uint_as_float(lo);
            o[2 * j + 1] = __uint_as_float(hi);
        }
        o[0] += b0.x; o[1] += b0.y; o[2] += b0.z; o[3] += b0.w;
        o[4] += b1.x; o[5] += b1.y; o[6] += b1.z; o[7] += b1.w;

        float p1 = o[0]*a10.x + o[1]*a10.y + o[2]*a10.z + o[3]*a10.w
                 + o[4]*a11.x + o[5]*a11.y + o[6]*a11.z + o[7]*a11.w;
        float p2 = o[0]*a20.x + o[1]*a20.y + o[2]*a20.z + o[3]*a20.w
                 + o[4]*a21.x + o[5]*a21.y + o[6]*a21.z + o[7]*a21.w;
        #pragma unroll
        for (int off = 4; off; off >>= 1) {
            p1 += __shfl_down_sync(0xffffffffu, p1, off, 8);
            p2 += __shfl_down_sync(0xffffffffu, p2, off, 8);
        }
        if (node < n_nodes) {
            __half2 pk[4];
            pk[0] = __floats2half2_rn(o[0], o[1]);
            pk[1] = __floats2half2_rn(o[2], o[3]);
            pk[2] = __floats2half2_rn(o[4], o[5]);
            pk[3] = __floats2half2_rn(o[6], o[7]);
            *(uint4*)(g_whh + (size_t)node * OUT_DIM + tx * 8) = *(uint4*)pk;
            if (tx == 0) { g_srow[node] = p1; g_scol[node] = p2; }
        }
    }

    // ---- fused degree histogram (grid-stride, coalesced) ----
    int stride = gridDim.x * 64;
    for (int e = blockIdx.x * 64 + t; e < n_edges; e += stride) {
        long long r = load_idx(ei, e);
        if (r >= 0 && r < n_nodes) atomicAdd(&g_deg[(int)r], 1);
    }
}

// ---------------------------------------------------------------------------
// Scan stage 1: per-block exclusive scan; raw block sums -> g_bsum
// ---------------------------------------------------------------------------
__global__ __launch_bounds__(SCAN_BLK) void k_scan1(int n) {
    __shared__ int wsum[32];
    int tid = threadIdx.x;
    int gi = blockIdx.x * SCAN_BLK + tid;
    int v = (gi < n) ? g_deg[gi] : 0;
    int lane = tid & 31, wid = tid >> 5;
    int x = v;
    #pragma unroll
    for (int o = 1; o < 32; o <<= 1) {
        int y = __shfl_up_sync(0xffffffffu, x, o);
        if (lane >= o) x += y;
    }
    if (lane == 31) wsum[wid] = x;
    __syncthreads();
    if (wid == 0) {
        int s = (lane < SCAN_BLK / 32) ? wsum[lane] : 0;
        #pragma unroll
        for (int o = 1; o < 32; o <<= 1) {
            int y = __shfl_up_sync(0xffffffffu, s, o);
            if (lane >= o) s += y;
        }
        wsum[lane] = s;
    }
    __syncthreads();
    int pre = (wid > 0) ? wsum[wid - 1] : 0;
    int incl = pre + x;
    if (gi < n) g_start[gi] = incl - v;
    if (tid == SCAN_BLK - 1) g_bsum[blockIdx.x] = incl;
}

// ---------------------------------------------------------------------------
// Scan stage 2 (merged): each block re-scans raw block sums in shared
// (nb <= 224 values) and applies its prefix.
// ---------------------------------------------------------------------------
__global__ __launch_bounds__(256) void k_scan3(int n, int nb) {
    __shared__ int s_pref[224];
    int tid = threadIdx.x;
    if (tid < 32) {
        int run = 0;
        for (int base = 0; base < nb; base += 32) {
            int idx = base + tid;
            int v = (idx < nb) ? g_bsum[idx] : 0;
            int x = v;
            #pragma unroll
            for (int o = 1; o < 32; o <<= 1) {
                int y = __shfl_up_sync(0xffffffffu, x, o);
                if (tid >= o) x += y;
            }
            if (idx < nb) s_pref[idx] = run + x - v;     // exclusive
            run += __shfl_sync(0xffffffffu, x, 31);
        }
    }
    __syncthreads();
    int i = blockIdx.x * 256 + tid;
    if (i >= n) return;
    int s = g_start[i] + s_pref[i / SCAN_BLK];
    g_start[i] = s;
    g_cursor[i] = s;
}

// ---------------------------------------------------------------------------
// Fill: alpha = exp(leaky_relu(srow[r]+scol[c]+ea@a3+a_b)); bucket by row.
// ---------------------------------------------------------------------------
__global__ __launch_bounds__(256) void k_fill(
    const void* __restrict__ ei, const float* __restrict__ ea,
    const float* __restrict__ a_w, const float* __restrict__ a_b,
    int n_edges, int n_nodes)
{
    int e = blockIdx.x * 256 + threadIdx.x;
    if (e >= n_edges) return;
    long long r = load_idx(ei, e);
    long long c = load_idx(ei, (size_t)n_edges + e);
    if (r < 0 || r >= n_nodes || c < 0 || c >= n_nodes) return;

    float4 x0 = ((const float4*)ea)[e * 2];
    float4 x1 = ((const float4*)ea)[e * 2 + 1];
    float4 a30 = *(const float4*)(a_w + 2 * OUT_DIM);
    float4 a31 = *(const float4*)(a_w + 2 * OUT_DIM + 4);

    float s = g_srow[r] + g_scol[c] + a_b[0]
            + x0.x * a30.x + x0.y * a30.y + x0.z * a30.z + x0.w * a30.w
            + x1.x * a31.x + x1.y * a31.y + x1.z * a31.z + x1.w * a31.w;
    float ev = s > 0.f ? s : 0.01f * s;
    float alpha = __expf(fminf(ev, 80.f));   // overflow insurance; ratios exact

    int pos = atomicAdd(&g_cursor[(int)r], 1);
    g_pair[pos] = make_int2((int)c, __float_as_int(alpha));
}

// ---------------------------------------------------------------------------
// Reduce: 8 lanes per node (4 nodes/warp), fp16 rows gathered with 16B loads.
// Unroll 8 (was 4): doubles in-flight gathers per warp (16 -> 32) against the
// measured latency bound. Only change vs the 136.8us best.
// ---------------------------------------------------------------------------
__global__ __launch_bounds__(256) void k_reduce(float* __restrict__ out, int n_nodes) {
    int gid = blockIdx.x * 256 + threadIdx.x;
    int node = gid >> 3;
    int lane = threadIdx.x & 7;
    if (node >= n_nodes) return;

    int s = g_start[node];
    int d = g_deg[node];
    const uint4* wh = (const uint4*)g_whh;   // 8 uint4 per node row (128B)

    float acc[8] = {0.f, 0.f, 0.f, 0.f, 0.f, 0.f, 0.f, 0.f};
    float norm = 0.f;

#define EDGE_ACC(wv, av)                                                    \
    do {                                                                    \
        const __half2* hp = (const __half2*)&(wv);                          \
        float2 f0 = __half22float2(hp[0]);                                  \
        float2 f1 = __half22float2(hp[1]);                                  \
        float2 f2 = __half22float2(hp[2]);                                  \
        float2 f3 = __half22float2(hp[3]);                                  \
        acc[0] += (av) * f0.x; acc[1] += (av) * f0.y;                       \
        acc[2] += (av) * f1.x; acc[3] += (av) * f1.y;                       \
        acc[4] += (av) * f2.x; acc[5] += (av) * f2.y;                       \
        acc[6] += (av) * f3.x; acc[7] += (av) * f3.y;                       \
        norm += (av);                                                       \
    } while (0)

#define EDGE_LDACC(colv, av)                                                \
    do {                                                                    \
        uint4 wv = wh[(unsigned)(colv) * 8u + lane];                        \
        EDGE_ACC(wv, av);                                                   \
    } while (0)

    int j = 0;
    if ((s & 1) && d > 0) {                       // peel to 16B pair alignment
        int2 p = g_pair[s];
        EDGE_LDACC(p.x, __int_as_float(p.y));
        j = 1;
    }
    for (; j + 8 <= d; j += 8) {                  // 8-edge body: 4 pair loads,
        int4 q0 = *(const int4*)&g_pair[s + j];       // 8 gathers in flight
        int4 q1 = *(const int4*)&g_pair[s + j + 2];
        int4 q2 = *(const int4*)&g_pair[s + j + 4];
        int4 q3 = *(const int4*)&g_pair[s + j + 6];
        uint4 w0 = wh[(unsigned)q0.x * 8u + lane];
        uint4 w1 = wh[(unsigned)q0.z * 8u + lane];
        uint4 w2 = wh[(unsigned)q1.x * 8u + lane];
        uint4 w3 = wh[(unsigned)q1.z * 8u + lane];
        uint4 w4 = wh[(unsigned)q2.x * 8u + lane];
        uint4 w5 = wh[(unsigned)q2.z * 8u + lane];
        uint4 w6 = wh[(unsigned)q3.x * 8u + lane];
        uint4 w7 = wh[(unsigned)q3.z * 8u + lane];
        EDGE_ACC(w0, __int_as_float(q0.y));
        EDGE_ACC(w1, __int_as_float(q0.w));
        EDGE_ACC(w2, __int_as_float(q1.y));
        EDGE_ACC(w3, __int_as_float(q1.w));
        EDGE_ACC(w4, __int_as_float(q2.y));
        EDGE_ACC(w5, __int_as_float(q2.w));
        EDGE_ACC(w6, __int_as_float(q3.y));
        EDGE_ACC(w7, __int_as_float(q3.w));
    }
    for (; j + 2 <= d; j += 2) {
        int4 q = *(const int4*)&g_pair[s + j];
        uint4 w0 = wh[(unsigned)q.x * 8u + lane];
        uint4 w1 = wh[(unsigned)q.z * 8u + lane];
        EDGE_ACC(w0, __int_as_float(q.y));
        EDGE_ACC(w1, __int_as_float(q.w));
    }
    if (j < d) {
        int2 p = g_pair[s + j];
        EDGE_LDACC(p.x, __int_as_float(p.y));
    }
#undef EDGE_LDACC
#undef EDGE_ACC

    float inv = 1.f / (norm + 1e-8f);
    float4* dst = (float4*)(out + (size_t)node * OUT_DIM + lane * 8);
    dst[0] = make_float4(acc[0] * inv, acc[1] * inv, acc[2] * inv, acc[3] * inv);
    dst[1] = make_float4(acc[4] * inv, acc[5] * inv, acc[6] * inv, acc[7] * inv);
}

// ---------------------------------------------------------------------------
extern "C" void kernel_launch(void* const* d_in, const int* in_sizes, int n_in,
                              void* d_out, int out_size)
{
    const float* h   = (const float*)d_in[0];
    const void*  ei  = d_in[1];
    const float* ea  = (const float*)d_in[2];
    const float* w_w = (const float*)d_in[3];
    const float* w_b = (const float*)d_in[4];
    const float* a_w = (const float*)d_in[5];
    const float* a_b = (const float*)d_in[6];
    float* out = (float*)d_out;

    int n_nodes = in_sizes[0] / IN_DIM;
    int n_edges = in_sizes[2] / 8;
    int nb = (n_nodes + SCAN_BLK - 1) / SCAN_BLK;

    k_prep  <<<(n_nodes + 255) / 256, 256>>>(ei, n_nodes);
    k_gemm  <<<(n_nodes + 63) / 64, 64>>>(h, w_w, w_b, a_w, ei, n_nodes, n_edges);
    k_scan1 <<<nb, SCAN_BLK>>>(n_nodes);
    k_scan3 <<<(n_nodes + 255) / 256, 256>>>(n_nodes, nb);
    k_fill  <<<(n_edges + 255) / 256, 256>>>(ei, ea, a_w, a_b, n_edges, n_nodes);
    k_reduce<<<(n_nodes * 8 + 255) / 256, 256>>>(out, n_nodes);
}